// round 1
// baseline (speedup 1.0000x reference)
#include <cuda_runtime.h>

#define NB 16
#define NT 512
#define ND 384
#define MAXLEN 4096
#define NVEC (ND / 4)   // 96 float4 per row; 96 % 32 == 0 -> warp-aligned rows

// Scratch: token index per (batch, mel position); -1 marks padded/zero rows.
__device__ int g_tok[NB * MAXLEN];

// Kernel A: per-batch inclusive scan of durations + scatter token ids.
__global__ void __launch_bounds__(NT) scan_scatter_kernel(
    const int* __restrict__ dur, float* __restrict__ mel_out, int write_mel)
{
    __shared__ int s[NT];
    const int b = blockIdx.x;
    const int t = threadIdx.x;

    const int d = dur[b * NT + t];
    s[t] = d;
    __syncthreads();

    // Hillis-Steele inclusive scan over 512 elements (9 steps)
    #pragma unroll
    for (int off = 1; off < NT; off <<= 1) {
        int v = (t >= off) ? s[t - off] : 0;
        __syncthreads();
        if (t >= off) s[t] += v;
        __syncthreads();
    }

    const int cum   = s[t];          // inclusive cumsum at token t
    const int start = cum - d;       // first mel position covered by token t
    const int mel   = s[NT - 1];     // total mel length for this batch
    const int L     = mel < MAXLEN ? mel : MAXLEN;

    int* tok_b = g_tok + b * MAXLEN;

    // Scatter: positions [start, min(cum, MAXLEN)) belong to token t.
    // durations < 8, so at most 7 iterations per thread.
    const int end = cum < MAXLEN ? cum : MAXLEN;
    for (int p = start; p < end; ++p) tok_b[p] = t;

    // Tail: positions >= min(mel_len, max_len) are zeroed rows.
    for (int p = L + t; p < MAXLEN; p += NT) tok_b[p] = -1;

    if (write_mel && t == 0) mel_out[b] = (float)mel;
}

// Kernel B: vectorized gather-copy. Each warp handles 32 consecutive float4
// of exactly one output row (96 f4/row, 96 % 32 == 0), so the g_tok load is a
// uniform broadcast and both read and write are fully coalesced.
__global__ void __launch_bounds__(256) expand_kernel(
    const float4* __restrict__ enc, float4* __restrict__ out)
{
    const int idx = blockIdx.x * blockDim.x + threadIdx.x;  // < NB*MAXLEN*NVEC exactly
    const int row = idx / NVEC;               // (b, pos) flat index
    const int c   = idx - row * NVEC;         // float4 column within row
    const int tok = __ldg(&g_tok[row]);
    const int b   = row >> 12;                // MAXLEN == 4096

    float4 v;
    if (tok < 0) {
        v = make_float4(0.f, 0.f, 0.f, 0.f);
    } else {
        v = enc[(b * NT + tok) * NVEC + c];
    }
    out[idx] = v;
}

extern "C" void kernel_launch(void* const* d_in, const int* in_sizes, int n_in,
                              void* d_out, int out_size)
{
    const float* enc = (const float*)d_in[0];   // (16, 512, 384) f32
    const int*   dur = (const int*)d_in[1];     // (16, 512) i32
    // d_in[2] = max_len scalar (fixed at 4096; compile-time constant)

    float* out = (float*)d_out;
    const long long main_elems = (long long)NB * MAXLEN * ND;  // 25,165,824

    // If the harness concatenated mel_lens after expanded, write them too.
    const int write_mel = (out_size > main_elems) ? 1 : 0;
    float* mel_out = out + main_elems;

    scan_scatter_kernel<<<NB, NT>>>(dur, mel_out, write_mel);

    const int total_vec = NB * MAXLEN * NVEC;   // 6,291,456
    expand_kernel<<<total_vec / 256, 256>>>((const float4*)enc, (float4*)out);
}

// round 4
// speedup vs baseline: 1.3103x; 1.3103x over previous
#include <cuda_runtime.h>

#define NB 16
#define NT 512
#define ND 384
#define MAXLEN 4096
#define NVEC (ND / 4)        // 96 float4 per row
#define ROWS_PER_WARP 2
#define WARPS_PER_BLK 8      // 256 threads
// total rows = NB*MAXLEN = 65536; warps = 32768; blocks = 4096

// Scratch: token index per (batch, mel position); -1 marks padded/zero rows.
__device__ int g_tok[NB * MAXLEN];

// Kernel A: per-batch inclusive scan of durations + scatter token ids.
__global__ void __launch_bounds__(NT) scan_scatter_kernel(
    const int* __restrict__ dur, float* __restrict__ mel_out, int write_mel)
{
    __shared__ int s[NT];
    const int b = blockIdx.x;
    const int t = threadIdx.x;

    const int d = dur[b * NT + t];
    s[t] = d;
    __syncthreads();

    // Hillis-Steele inclusive scan over 512 elements (9 steps)
    #pragma unroll
    for (int off = 1; off < NT; off <<= 1) {
        int v = (t >= off) ? s[t - off] : 0;
        __syncthreads();
        if (t >= off) s[t] += v;
        __syncthreads();
    }

    const int cum   = s[t];          // inclusive cumsum at token t
    const int start = cum - d;       // first mel position covered by token t
    const int mel   = s[NT - 1];     // total mel length for this batch
    const int L     = mel < MAXLEN ? mel : MAXLEN;

    int* tok_b = g_tok + b * MAXLEN;

    const int end = cum < MAXLEN ? cum : MAXLEN;
    for (int p = start; p < end; ++p) tok_b[p] = t;   // durations < 8 -> <=7 iters

    for (int p = L + t; p < MAXLEN; p += NT) tok_b[p] = -1;

    if (write_mel && t == 0) mel_out[b] = (float)mel;
}

// Kernel B: each warp copies ROWS_PER_WARP full output rows.
// All loads for both rows are hoisted before any store -> 6 outstanding
// LDG.128 per thread (MLP=6). Stores use streaming hint so the 100MB output
// does not evict the 12.6MB encoder working set from L2.
__global__ void __launch_bounds__(WARPS_PER_BLK * 32) expand_kernel(
    const float4* __restrict__ enc, float4* __restrict__ out)
{
    const int warp = blockIdx.x * WARPS_PER_BLK + (threadIdx.x >> 5);
    const int lane = threadIdx.x & 31;

    const int row0 = warp * ROWS_PER_WARP;
    const int row1 = row0 + 1;

    const int tok0 = g_tok[row0];
    const int tok1 = g_tok[row1];

    // source row base: (b * 512 + tok) * 96 ; b = row >> 12
    const float4* s0 = enc + ((size_t)((row0 >> 12) << 9) + (tok0 < 0 ? 0 : tok0)) * NVEC;
    const float4* s1 = enc + ((size_t)((row1 >> 12) << 9) + (tok1 < 0 ? 0 : tok1)) * NVEC;

    const float4 z = make_float4(0.f, 0.f, 0.f, 0.f);
    float4 a0 = z, a1 = z, a2 = z;
    float4 b0 = z, b1 = z, b2 = z;

    if (tok0 >= 0) {
        a0 = s0[lane];
        a1 = s0[lane + 32];
        a2 = s0[lane + 64];
    }
    if (tok1 >= 0) {
        b0 = s1[lane];
        b1 = s1[lane + 32];
        b2 = s1[lane + 64];
    }

    float4* d0 = out + (size_t)row0 * NVEC;
    float4* d1 = out + (size_t)row1 * NVEC;

    __stcs(d0 + lane,      a0);
    __stcs(d0 + lane + 32, a1);
    __stcs(d0 + lane + 64, a2);
    __stcs(d1 + lane,      b0);
    __stcs(d1 + lane + 32, b1);
    __stcs(d1 + lane + 64, b2);
}

extern "C" void kernel_launch(void* const* d_in, const int* in_sizes, int n_in,
                              void* d_out, int out_size)
{
    const float* enc = (const float*)d_in[0];   // (16, 512, 384) f32
    const int*   dur = (const int*)d_in[1];     // (16, 512) i32

    float* out = (float*)d_out;
    const long long main_elems = (long long)NB * MAXLEN * ND;  // 25,165,824

    const int write_mel = (out_size > main_elems) ? 1 : 0;
    float* mel_out = out + main_elems;

    scan_scatter_kernel<<<NB, NT>>>(dur, mel_out, write_mel);

    const int total_warps = (NB * MAXLEN) / ROWS_PER_WARP;          // 32768
    expand_kernel<<<total_warps / WARPS_PER_BLK, WARPS_PER_BLK * 32>>>(
        (const float4*)enc, (float4*)out);
}

// round 8
// speedup vs baseline: 1.3902x; 1.0610x over previous
#include <cuda_runtime.h>

#define NB 16
#define NT 512
#define ND 384
#define MAXLEN 4096
#define NVEC (ND / 4)        // 96 float4 per row
#define ROWS_PER_WARP 4
#define WARPS_PER_BLK 8      // 256 threads
// total rows = NB*MAXLEN = 65536; warps = 16384; blocks = 2048

// Scratch: token index per (batch, mel position); -1 marks padded/zero rows.
__device__ int g_tok[NB * MAXLEN];

// Kernel A: per-batch inclusive scan of durations (two-level shfl) + scatter.
__global__ void __launch_bounds__(NT) scan_scatter_kernel(
    const int* __restrict__ dur, float* __restrict__ mel_out, int write_mel)
{
    __shared__ int part[NT / 32];   // 16 warp partials
    const int b    = blockIdx.x;
    const int t    = threadIdx.x;
    const int wid  = t >> 5;
    const int lane = t & 31;

    const int d = dur[b * NT + t];

    // warp-level inclusive scan
    int v = d;
    #pragma unroll
    for (int off = 1; off < 32; off <<= 1) {
        int n = __shfl_up_sync(0xFFFFFFFFu, v, off);
        if (lane >= off) v += n;
    }
    if (lane == 31) part[wid] = v;
    __syncthreads();

    // warp 0 scans the 16 partials
    if (wid == 0) {
        int p = (lane < 16) ? part[lane] : 0;
        #pragma unroll
        for (int off = 1; off < 16; off <<= 1) {
            int n = __shfl_up_sync(0xFFFFFFFFu, p, off, 16);
            if ((lane & 15) >= off) p += n;
        }
        if (lane < 16) part[lane] = p;
    }
    __syncthreads();

    const int cum   = v + (wid ? part[wid - 1] : 0);  // inclusive cumsum at t
    const int start = cum - d;
    const int mel   = part[(NT / 32) - 1];            // total mel length
    const int L     = mel < MAXLEN ? mel : MAXLEN;

    int* tok_b = g_tok + b * MAXLEN;

    const int end = cum < MAXLEN ? cum : MAXLEN;
    for (int p = start; p < end; ++p) tok_b[p] = t;   // durations < 8 -> <=7 iters

    for (int p = L + t; p < MAXLEN; p += NT) tok_b[p] = -1;

    if (write_mel && t == 0) mel_out[b] = (float)mel;
}

// Kernel B: each warp copies 4 consecutive output rows (96 f4 each).
// All 12 LDG.128 hoisted before the 12 streaming STG.128 (MLP=12).
// g_tok for the 4 rows loaded as one int4 (16B-aligned, uniform per warp).
__global__ void __launch_bounds__(WARPS_PER_BLK * 32) expand_kernel(
    const float4* __restrict__ enc, float4* __restrict__ out)
{
    const int warp = blockIdx.x * WARPS_PER_BLK + (threadIdx.x >> 5);
    const int lane = threadIdx.x & 31;
    const int row0 = warp * ROWS_PER_WARP;

    // Prologue done; wait for scan kernel's results (PDL overlap point).
    cudaGridDependencySynchronize();

    const int4 tk = *reinterpret_cast<const int4*>(&g_tok[row0]);

    // source row base: (b * 512 + tok) * 96 ; b = row >> 12 (same for all 4
    // rows: row0 is a multiple of 4, batch boundaries are multiples of 4096)
    const size_t bbase = (size_t)((row0 >> 12) << 9) * NVEC;
    const float4* s0 = enc + bbase + (size_t)(tk.x < 0 ? 0 : tk.x) * NVEC;
    const float4* s1 = enc + bbase + (size_t)(tk.y < 0 ? 0 : tk.y) * NVEC;
    const float4* s2 = enc + bbase + (size_t)(tk.z < 0 ? 0 : tk.z) * NVEC;
    const float4* s3 = enc + bbase + (size_t)(tk.w < 0 ? 0 : tk.w) * NVEC;

    const float4 z = make_float4(0.f, 0.f, 0.f, 0.f);
    float4 a0 = z, a1 = z, a2 = z;
    float4 b0 = z, b1 = z, b2 = z;
    float4 c0 = z, c1 = z, c2 = z;
    float4 d0 = z, d1 = z, d2 = z;

    if (tk.x >= 0) { a0 = s0[lane]; a1 = s0[lane + 32]; a2 = s0[lane + 64]; }
    if (tk.y >= 0) { b0 = s1[lane]; b1 = s1[lane + 32]; b2 = s1[lane + 64]; }
    if (tk.z >= 0) { c0 = s2[lane]; c1 = s2[lane + 32]; c2 = s2[lane + 64]; }
    if (tk.w >= 0) { d0 = s3[lane]; d1 = s3[lane + 32]; d2 = s3[lane + 64]; }

    float4* o = out + (size_t)row0 * NVEC;

    __stcs(o + lane,            a0);
    __stcs(o + lane + 32,       a1);
    __stcs(o + lane + 64,       a2);
    __stcs(o + lane + 96,       b0);
    __stcs(o + lane + 128,      b1);
    __stcs(o + lane + 160,      b2);
    __stcs(o + lane + 192,      c0);
    __stcs(o + lane + 224,      c1);
    __stcs(o + lane + 256,      c2);
    __stcs(o + lane + 288,      d0);
    __stcs(o + lane + 320,      d1);
    __stcs(o + lane + 352,      d2);
}

extern "C" void kernel_launch(void* const* d_in, const int* in_sizes, int n_in,
                              void* d_out, int out_size)
{
    const float* enc = (const float*)d_in[0];   // (16, 512, 384) f32
    const int*   dur = (const int*)d_in[1];     // (16, 512) i32

    float* out = (float*)d_out;
    const long long main_elems = (long long)NB * MAXLEN * ND;  // 25,165,824

    const int write_mel = (out_size > main_elems) ? 1 : 0;
    float* mel_out = out + main_elems;

    scan_scatter_kernel<<<NB, NT>>>(dur, mel_out, write_mel);

    // Expand kernel with Programmatic Dependent Launch: blocks come resident
    // and run their prologue while the scan kernel drains; they block at
    // cudaGridDependencySynchronize() until the scan's writes are visible.
    const int total_warps = (NB * MAXLEN) / ROWS_PER_WARP;      // 16384
    cudaLaunchConfig_t cfg = {};
    cfg.gridDim  = dim3(total_warps / WARPS_PER_BLK, 1, 1);     // 2048
    cfg.blockDim = dim3(WARPS_PER_BLK * 32, 1, 1);
    cudaLaunchAttribute attr[1];
    attr[0].id = cudaLaunchAttributeProgrammaticStreamSerialization;
    attr[0].val.programmaticStreamSerializationAllowed = 1;
    cfg.attrs    = attr;
    cfg.numAttrs = 1;
    cudaLaunchKernelEx(&cfg, expand_kernel, (const float4*)enc, (float4*)out);
}